// round 1
// baseline (speedup 1.0000x reference)
#include <cuda_runtime.h>

#define BATCH 4
#define SEQ   2048
#define EMBD  1024
#define HEADS 16
#define HDIM  64
#define MTOT  (BATCH*SEQ)   // 8192

// -------- scratch (static device globals; no runtime allocation) ----------
__device__ float g_Q[BATCH*SEQ*EMBD];   // Q projection [B*S, E] (== [B,S,H,Dh])
__device__ float g_K[BATCH*SEQ*HDIM];   // shared K     [B*S, Dh]
__device__ float g_V[BATCH*SEQ*HDIM];   // shared V     [B*S, Dh]
__device__ float g_A[BATCH*SEQ*EMBD];   // attention output (pre-Wo)

// ---------------------------------------------------------------------------
// Tiled SGEMM: C[M,N] = A[M,K] @ B[K,N] + bias[N]
// 64x64 block tile, K-tile 16, 256 threads, 4x4 register micro-tile.
// ---------------------------------------------------------------------------
__global__ __launch_bounds__(256) void sgemm_bias(
    const float* __restrict__ A, const float* __restrict__ Bm,
    const float* __restrict__ bias, float* __restrict__ C,
    int M, int N, int K)
{
    __shared__ float As[16][64];   // As[k][m] (A transposed in smem)
    __shared__ float Bs[16][64];   // Bs[k][n]

    const int tid = threadIdx.x;
    const int tx  = tid & 15;      // n direction
    const int ty  = tid >> 4;      // m direction
    const int m0  = blockIdx.y * 64;
    const int n0  = blockIdx.x * 64;

    float acc[4][4] = {};

    for (int k0 = 0; k0 < K; k0 += 16) {
        // load A tile (64 rows x 16 k), store transposed
        {
            int m = tid >> 2;
            int k = (tid & 3) * 4;
            float4 a = *(const float4*)&A[(m0 + m) * K + k0 + k];
            As[k + 0][m] = a.x; As[k + 1][m] = a.y;
            As[k + 2][m] = a.z; As[k + 3][m] = a.w;
        }
        // load B tile (16 k x 64 n), coalesced float4
        {
            int k = tid >> 4;
            int n = (tid & 15) * 4;
            *(float4*)&Bs[k][n] = *(const float4*)&Bm[(k0 + k) * N + n0 + n];
        }
        __syncthreads();

        #pragma unroll
        for (int k = 0; k < 16; k++) {
            float4 a4 = *(float4*)&As[k][ty * 4];
            float4 b4 = *(float4*)&Bs[k][tx * 4];
            float av[4] = {a4.x, a4.y, a4.z, a4.w};
            float bv[4] = {b4.x, b4.y, b4.z, b4.w};
            #pragma unroll
            for (int i = 0; i < 4; i++)
                #pragma unroll
                for (int j = 0; j < 4; j++)
                    acc[i][j] += av[i] * bv[j];
        }
        __syncthreads();
    }

    #pragma unroll
    for (int i = 0; i < 4; i++) {
        int m = m0 + ty * 4 + i;
        #pragma unroll
        for (int j = 0; j < 4; j++) {
            int n = n0 + tx * 4 + j;
            C[m * N + n] = acc[i][j] + bias[n];
        }
    }
}

// ---------------------------------------------------------------------------
// Flash attention (multiquery: K/V shared across heads).
// One CTA per (q_tile of 64, head, batch). Br = Bc = 64, Dh = 64.
// Online softmax; 256 threads; each thread owns a 4x4 micro-tile of S and O.
// Dynamic smem: Qs[64][68], Ks[64][68], Ps[64][68], Vs[64][64]  = 68608 B
// ---------------------------------------------------------------------------
#define QS_STRIDE 68
#define KS_STRIDE 68
#define PS_STRIDE 68
#define VS_STRIDE 64
#define FLASH_SMEM ((3 * 64 * 68 + 64 * 64) * 4)

__global__ __launch_bounds__(256) void mqa_flash(
    const float* __restrict__ Q, const float* __restrict__ Kg,
    const float* __restrict__ Vg, float* __restrict__ O)
{
    extern __shared__ float smem[];
    float* Qs = smem;                       // 64 x 68
    float* Ks = Qs + 64 * QS_STRIDE;        // 64 x 68
    float* Ps = Ks + 64 * KS_STRIDE;        // 64 x 68
    float* Vs = Ps + 64 * PS_STRIDE;        // 64 x 64

    const int tid = threadIdx.x;
    const int tx  = tid & 15;               // key / dh direction
    const int ty  = tid >> 4;               // query direction
    const int q0  = blockIdx.x * 64;
    const int h   = blockIdx.y;
    const int b   = blockIdx.z;
    const float scale = 0.125f;             // 1/sqrt(64)

    // load Q tile: rows = queries, cols = head dims (float4)
    for (int e = tid; e < 64 * 16; e += 256) {
        int r  = e >> 4;
        int c4 = (e & 15) * 4;
        *(float4*)&Qs[r * QS_STRIDE + c4] =
            *(const float4*)&Q[(b * SEQ + q0 + r) * EMBD + h * HDIM + c4];
    }

    float o[4][4] = {};
    float m_i[4], l_i[4];
    #pragma unroll
    for (int i = 0; i < 4; i++) { m_i[i] = -1e30f; l_i[i] = 0.f; }

    for (int kt = 0; kt < SEQ; kt += 64) {
        // load K, V tiles (64 keys x 64 dims)
        for (int e = tid; e < 64 * 16; e += 256) {
            int r  = e >> 4;
            int c4 = (e & 15) * 4;
            int g  = (b * SEQ + kt + r) * HDIM + c4;
            *(float4*)&Ks[r * KS_STRIDE + c4] = *(const float4*)&Kg[g];
            *(float4*)&Vs[r * VS_STRIDE + c4] = *(const float4*)&Vg[g];
        }
        __syncthreads();

        // S = (Q @ K^T) * scale  -> per-thread 4x4
        float sv[4][4] = {};
        #pragma unroll
        for (int kk = 0; kk < 16; kk++) {
            float4 qv[4], kv[4];
            #pragma unroll
            for (int i = 0; i < 4; i++)
                qv[i] = *(float4*)&Qs[(ty * 4 + i) * QS_STRIDE + kk * 4];
            #pragma unroll
            for (int j = 0; j < 4; j++)
                kv[j] = *(float4*)&Ks[(tx * 4 + j) * KS_STRIDE + kk * 4];
            #pragma unroll
            for (int i = 0; i < 4; i++)
                #pragma unroll
                for (int j = 0; j < 4; j++)
                    sv[i][j] += qv[i].x * kv[j].x + qv[i].y * kv[j].y +
                                qv[i].z * kv[j].z + qv[i].w * kv[j].w;
        }

        // online softmax update (row stats reduced across the 16 tx-lanes)
        #pragma unroll
        for (int i = 0; i < 4; i++) {
            #pragma unroll
            for (int j = 0; j < 4; j++) sv[i][j] *= scale;

            float mx = fmaxf(fmaxf(sv[i][0], sv[i][1]), fmaxf(sv[i][2], sv[i][3]));
            #pragma unroll
            for (int off = 8; off >= 1; off >>= 1)
                mx = fmaxf(mx, __shfl_xor_sync(0xffffffffu, mx, off));

            float mnew  = fmaxf(m_i[i], mx);
            float alpha = __expf(m_i[i] - mnew);

            float rsum = 0.f;
            #pragma unroll
            for (int j = 0; j < 4; j++) {
                float p = __expf(sv[i][j] - mnew);
                Ps[(ty * 4 + i) * PS_STRIDE + tx * 4 + j] = p;
                rsum += p;
            }
            #pragma unroll
            for (int off = 8; off >= 1; off >>= 1)
                rsum += __shfl_xor_sync(0xffffffffu, rsum, off);

            l_i[i] = l_i[i] * alpha + rsum;
            m_i[i] = mnew;
            #pragma unroll
            for (int j = 0; j < 4; j++) o[i][j] *= alpha;
        }
        __syncthreads();   // Ps visible to all

        // O += P @ V   (o cols = head dims tx*4..tx*4+3)
        #pragma unroll 4
        for (int c = 0; c < 64; c++) {
            float4 v4 = *(float4*)&Vs[c * VS_STRIDE + tx * 4];
            #pragma unroll
            for (int i = 0; i < 4; i++) {
                float p = Ps[(ty * 4 + i) * PS_STRIDE + c];
                o[i][0] += p * v4.x; o[i][1] += p * v4.y;
                o[i][2] += p * v4.z; o[i][3] += p * v4.w;
            }
        }
        __syncthreads();   // done with Ks/Vs/Ps before next tile load
    }

    // normalize and write back into [B,S,H*Dh] layout
    #pragma unroll
    for (int i = 0; i < 4; i++) {
        float inv = 1.f / l_i[i];
        float4 res = make_float4(o[i][0] * inv, o[i][1] * inv,
                                 o[i][2] * inv, o[i][3] * inv);
        *(float4*)&O[(b * SEQ + q0 + ty * 4 + i) * EMBD + h * HDIM + tx * 4] = res;
    }
}

// ---------------------------------------------------------------------------
extern "C" void kernel_launch(void* const* d_in, const int* in_sizes, int n_in,
                              void* d_out, int out_size)
{
    const float* x  = (const float*)d_in[0];
    const float* Wq = (const float*)d_in[1];
    const float* bq = (const float*)d_in[2];
    const float* Wk = (const float*)d_in[3];
    const float* bk = (const float*)d_in[4];
    const float* Wv = (const float*)d_in[5];
    const float* bv = (const float*)d_in[6];
    const float* Wo = (const float*)d_in[7];
    const float* bo = (const float*)d_in[8];
    float* out = (float*)d_out;

    float *Q, *Kb, *Vb, *Ab;
    cudaGetSymbolAddress((void**)&Q,  g_Q);
    cudaGetSymbolAddress((void**)&Kb, g_K);
    cudaGetSymbolAddress((void**)&Vb, g_V);
    cudaGetSymbolAddress((void**)&Ab, g_A);

    // projections
    sgemm_bias<<<dim3(EMBD / 64, MTOT / 64), 256>>>(x, Wq, bq, Q,  MTOT, EMBD, EMBD);
    sgemm_bias<<<dim3(1,         MTOT / 64), 256>>>(x, Wk, bk, Kb, MTOT, HDIM, EMBD);
    sgemm_bias<<<dim3(1,         MTOT / 64), 256>>>(x, Wv, bv, Vb, MTOT, HDIM, EMBD);

    // flash attention
    cudaFuncSetAttribute(mqa_flash, cudaFuncAttributeMaxDynamicSharedMemorySize,
                         FLASH_SMEM);
    mqa_flash<<<dim3(SEQ / 64, HEADS, BATCH), 256, FLASH_SMEM>>>(Q, Kb, Vb, Ab);

    // output projection
    sgemm_bias<<<dim3(EMBD / 64, MTOT / 64), 256>>>(Ab, Wo, bo, out, MTOT, EMBD, EMBD);
}

// round 2
// speedup vs baseline: 4.1233x; 4.1233x over previous
#include <cuda_runtime.h>

#define BATCH 4
#define SEQ   2048
#define EMBD  1024
#define HEADS 16
#define HDIM  64
#define MTOT  (BATCH*SEQ)   // 8192

// -------- scratch (static device globals; no runtime allocation) ----------
__device__ float g_Q[BATCH*SEQ*EMBD];   // Q projection [B*S, E]
__device__ float g_K[BATCH*SEQ*HDIM];   // shared K     [B*S, Dh]
__device__ float g_V[BATCH*SEQ*HDIM];   // shared V     [B*S, Dh]
__device__ float g_A[BATCH*SEQ*EMBD];   // attention output (pre-Wo)

// ---------------- tf32 helpers ----------------
__device__ __forceinline__ unsigned f2tf(float f) {
    unsigned u; asm("cvt.rna.tf32.f32 %0, %1;" : "=r"(u) : "f"(f)); return u;
}
__device__ __forceinline__ void mma8(float* c,
    unsigned a0, unsigned a1, unsigned a2, unsigned a3,
    unsigned b0, unsigned b1)
{
    asm volatile(
        "mma.sync.aligned.m16n8k8.row.col.f32.tf32.tf32.f32 "
        "{%0,%1,%2,%3}, {%4,%5,%6,%7}, {%8,%9}, {%0,%1,%2,%3};\n"
        : "+f"(c[0]), "+f"(c[1]), "+f"(c[2]), "+f"(c[3])
        : "r"(a0), "r"(a1), "r"(a2), "r"(a3), "r"(b0), "r"(b1));
}

// ---------------------------------------------------------------------------
// tf32 tensor-core GEMM: C[M,N] = A[M,K] @ B[K,N] + bias[N]
// BM=128, BN=64, BK=32. 256 threads = 8 warps (4m x 2n), warp tile 32x32.
// ---------------------------------------------------------------------------
#define APAD 36
#define BPAD 68

__global__ __launch_bounds__(256) void gemm_tf32(
    const float* __restrict__ A, const float* __restrict__ B,
    const float* __restrict__ bias, float* __restrict__ C,
    int M, int N, int K)
{
    __shared__ unsigned As[128 * APAD];   // As[row][k], tf32 bits
    __shared__ unsigned Bs[32 * BPAD];    // Bs[k][n],   tf32 bits

    const int tid = threadIdx.x;
    const int m0 = blockIdx.y * 128;
    const int n0 = blockIdx.x * 64;

    const int w    = tid >> 5;
    const int lane = tid & 31;
    const int wm   = w >> 1;          // 0..3
    const int wn   = w & 1;           // 0..1
    const int g    = lane >> 2;       // 0..7
    const int t    = lane & 3;        // 0..3
    const int mb0  = wm * 32;
    const int nb0  = wn * 32;

    float acc[2][4][4] = {};
    float4 pa[4]; float4 pb[2];

    const int nt = K / 32;

    // prefetch tile 0
    #pragma unroll
    for (int i = 0; i < 4; i++) {
        int idx = i * 256 + tid; int r = idx >> 3; int c = (idx & 7) * 4;
        pa[i] = *(const float4*)&A[(size_t)(m0 + r) * K + c];
    }
    #pragma unroll
    for (int i = 0; i < 2; i++) {
        int idx = i * 256 + tid; int r = idx >> 4; int c = (idx & 15) * 4;
        pb[i] = *(const float4*)&B[(size_t)r * N + n0 + c];
    }
    // store tile 0
    #pragma unroll
    for (int i = 0; i < 4; i++) {
        int idx = i * 256 + tid; int r = idx >> 3; int c = (idx & 7) * 4;
        uint4 u = { f2tf(pa[i].x), f2tf(pa[i].y), f2tf(pa[i].z), f2tf(pa[i].w) };
        *(uint4*)&As[r * APAD + c] = u;
    }
    #pragma unroll
    for (int i = 0; i < 2; i++) {
        int idx = i * 256 + tid; int r = idx >> 4; int c = (idx & 15) * 4;
        uint4 u = { f2tf(pb[i].x), f2tf(pb[i].y), f2tf(pb[i].z), f2tf(pb[i].w) };
        *(uint4*)&Bs[r * BPAD + c] = u;
    }
    __syncthreads();

    for (int kt = 0; kt < nt; kt++) {
        // prefetch next tile into registers (hides gmem latency under compute)
        if (kt + 1 < nt) {
            int k0 = (kt + 1) * 32;
            #pragma unroll
            for (int i = 0; i < 4; i++) {
                int idx = i * 256 + tid; int r = idx >> 3; int c = (idx & 7) * 4;
                pa[i] = *(const float4*)&A[(size_t)(m0 + r) * K + k0 + c];
            }
            #pragma unroll
            for (int i = 0; i < 2; i++) {
                int idx = i * 256 + tid; int r = idx >> 4; int c = (idx & 15) * 4;
                pb[i] = *(const float4*)&B[(size_t)(k0 + r) * N + n0 + c];
            }
        }

        // compute on current smem tile
        #pragma unroll
        for (int ks = 0; ks < 4; ks++) {
            const int kk = ks * 8;
            unsigned a[2][4], bf[4][2];
            #pragma unroll
            for (int mi = 0; mi < 2; mi++) {
                int r0 = mb0 + mi * 16 + g;
                a[mi][0] = As[r0 * APAD + kk + t];
                a[mi][1] = As[(r0 + 8) * APAD + kk + t];
                a[mi][2] = As[r0 * APAD + kk + t + 4];
                a[mi][3] = As[(r0 + 8) * APAD + kk + t + 4];
            }
            #pragma unroll
            for (int ni = 0; ni < 4; ni++) {
                bf[ni][0] = Bs[(kk + t) * BPAD + nb0 + ni * 8 + g];
                bf[ni][1] = Bs[(kk + t + 4) * BPAD + nb0 + ni * 8 + g];
            }
            #pragma unroll
            for (int mi = 0; mi < 2; mi++)
                #pragma unroll
                for (int ni = 0; ni < 4; ni++)
                    mma8(acc[mi][ni], a[mi][0], a[mi][1], a[mi][2], a[mi][3],
                         bf[ni][0], bf[ni][1]);
        }

        if (kt + 1 < nt) {
            __syncthreads();
            #pragma unroll
            for (int i = 0; i < 4; i++) {
                int idx = i * 256 + tid; int r = idx >> 3; int c = (idx & 7) * 4;
                uint4 u = { f2tf(pa[i].x), f2tf(pa[i].y), f2tf(pa[i].z), f2tf(pa[i].w) };
                *(uint4*)&As[r * APAD + c] = u;
            }
            #pragma unroll
            for (int i = 0; i < 2; i++) {
                int idx = i * 256 + tid; int r = idx >> 4; int c = (idx & 15) * 4;
                uint4 u = { f2tf(pb[i].x), f2tf(pb[i].y), f2tf(pb[i].z), f2tf(pb[i].w) };
                *(uint4*)&Bs[r * BPAD + c] = u;
            }
            __syncthreads();
        }
    }

    // epilogue: C-fragment layout rows {g, g+8}, cols {2t, 2t+1}
    #pragma unroll
    for (int mi = 0; mi < 2; mi++) {
        int row = m0 + mb0 + mi * 16 + g;
        #pragma unroll
        for (int ni = 0; ni < 4; ni++) {
            int col = n0 + nb0 + ni * 8 + 2 * t;
            float2 bb = *(const float2*)&bias[col];
            float2 r0 = { acc[mi][ni][0] + bb.x, acc[mi][ni][1] + bb.y };
            float2 r1 = { acc[mi][ni][2] + bb.x, acc[mi][ni][3] + bb.y };
            *(float2*)&C[(size_t)row * N + col]       = r0;
            *(float2*)&C[(size_t)(row + 8) * N + col] = r1;
        }
    }
}

// ---------------------------------------------------------------------------
// Flash attention, tf32 tensor cores, multiquery (K/V shared across heads).
// CTA = (q-tile 64, head, batch). 128 threads = 4 warps; warp owns 16 q-rows.
// Q fragments live in registers for the whole kernel. P stays in registers:
// C-fragment -> A-fragment transpose done with warp shuffles.
// ---------------------------------------------------------------------------
#define FPAD 68

__global__ __launch_bounds__(128) void mqa_flash_tc(
    const float* __restrict__ Q, const float* __restrict__ Kg,
    const float* __restrict__ Vg, float* __restrict__ O)
{
    __shared__ unsigned Ks[64 * FPAD];
    __shared__ unsigned Vs[64 * FPAD];

    const int tid  = threadIdx.x;
    const int lane = tid & 31;
    const int w    = tid >> 5;
    const int g    = lane >> 2;
    const int t    = lane & 3;
    const int q0   = blockIdx.x * 64;
    const int h    = blockIdx.y;
    const int b    = blockIdx.z;

    // stage Q tile through Ks (coalesced), then extract fragments
    #pragma unroll
    for (int i = 0; i < 8; i++) {
        int idx = i * 128 + tid; int r = idx >> 4; int c4 = (idx & 15) * 4;
        float4 v = *(const float4*)&Q[(size_t)(b * SEQ + q0 + r) * EMBD + h * HDIM + c4];
        uint4 u = { f2tf(v.x), f2tf(v.y), f2tf(v.z), f2tf(v.w) };
        *(uint4*)&Ks[r * FPAD + c4] = u;
    }
    __syncthreads();

    unsigned qf[8][4];
    {
        int qr = w * 16 + g;
        #pragma unroll
        for (int kb = 0; kb < 8; kb++) {
            qf[kb][0] = Ks[qr * FPAD + kb * 8 + t];
            qf[kb][1] = Ks[(qr + 8) * FPAD + kb * 8 + t];
            qf[kb][2] = Ks[qr * FPAD + kb * 8 + t + 4];
            qf[kb][3] = Ks[(qr + 8) * FPAD + kb * 8 + t + 4];
        }
    }
    __syncthreads();

    float oacc[8][4] = {};
    float m0v = -1e30f, m1v = -1e30f, l0 = 0.f, l1 = 0.f;

    const int srcA = (lane & 28) | ((lane & 3) >> 1);
    const int srcB = srcA | 2;
    const bool odd = (lane & 1) != 0;

    for (int kt = 0; kt < SEQ; kt += 64) {
        // load K and V tiles (tf32-converted at store time)
        #pragma unroll
        for (int i = 0; i < 8; i++) {
            int idx = i * 128 + tid; int r = idx >> 4; int c4 = (idx & 15) * 4;
            size_t gb = (size_t)(b * SEQ + kt + r) * HDIM + c4;
            float4 kv = *(const float4*)&Kg[gb];
            float4 vv = *(const float4*)&Vg[gb];
            uint4 uk = { f2tf(kv.x), f2tf(kv.y), f2tf(kv.z), f2tf(kv.w) };
            uint4 uv = { f2tf(vv.x), f2tf(vv.y), f2tf(vv.z), f2tf(vv.w) };
            *(uint4*)&Ks[r * FPAD + c4] = uk;
            *(uint4*)&Vs[r * FPAD + c4] = uv;
        }
        __syncthreads();

        // S = Q @ K^T  (warp: 16 x 64)
        float sacc[8][4] = {};
        #pragma unroll
        for (int nb = 0; nb < 8; nb++) {
            int krow = nb * 8 + g;
            #pragma unroll
            for (int kb = 0; kb < 8; kb++) {
                unsigned b0 = Ks[krow * FPAD + kb * 8 + t];
                unsigned b1 = Ks[krow * FPAD + kb * 8 + t + 4];
                mma8(sacc[nb], qf[kb][0], qf[kb][1], qf[kb][2], qf[kb][3], b0, b1);
            }
        }

        // online softmax (thread owns rows g and g+8 of the warp's 16)
        float mx0 = -1e30f, mx1 = -1e30f;
        #pragma unroll
        for (int nb = 0; nb < 8; nb++) {
            sacc[nb][0] *= 0.125f; sacc[nb][1] *= 0.125f;
            sacc[nb][2] *= 0.125f; sacc[nb][3] *= 0.125f;
            mx0 = fmaxf(mx0, fmaxf(sacc[nb][0], sacc[nb][1]));
            mx1 = fmaxf(mx1, fmaxf(sacc[nb][2], sacc[nb][3]));
        }
        mx0 = fmaxf(mx0, __shfl_xor_sync(0xffffffffu, mx0, 1));
        mx0 = fmaxf(mx0, __shfl_xor_sync(0xffffffffu, mx0, 2));
        mx1 = fmaxf(mx1, __shfl_xor_sync(0xffffffffu, mx1, 1));
        mx1 = fmaxf(mx1, __shfl_xor_sync(0xffffffffu, mx1, 2));

        float mn0 = fmaxf(m0v, mx0), mn1 = fmaxf(m1v, mx1);
        float al0 = __expf(m0v - mn0), al1 = __expf(m1v - mn1);
        m0v = mn0; m1v = mn1;

        float rs0 = 0.f, rs1 = 0.f;
        #pragma unroll
        for (int nb = 0; nb < 8; nb++) {
            sacc[nb][0] = __expf(sacc[nb][0] - mn0);
            sacc[nb][1] = __expf(sacc[nb][1] - mn0);
            sacc[nb][2] = __expf(sacc[nb][2] - mn1);
            sacc[nb][3] = __expf(sacc[nb][3] - mn1);
            rs0 += sacc[nb][0] + sacc[nb][1];
            rs1 += sacc[nb][2] + sacc[nb][3];
        }
        rs0 += __shfl_xor_sync(0xffffffffu, rs0, 1);
        rs0 += __shfl_xor_sync(0xffffffffu, rs0, 2);
        rs1 += __shfl_xor_sync(0xffffffffu, rs1, 1);
        rs1 += __shfl_xor_sync(0xffffffffu, rs1, 2);

        l0 = l0 * al0 + rs0;
        l1 = l1 * al1 + rs1;
        #pragma unroll
        for (int nb = 0; nb < 8; nb++) {
            oacc[nb][0] *= al0; oacc[nb][1] *= al0;
            oacc[nb][2] *= al1; oacc[nb][3] *= al1;
        }

        // O += P @ V  : transpose P C-frag -> A-frag via shuffles, then MMA
        #pragma unroll
        for (int kb = 0; kb < 8; kb++) {
            float p00 = __shfl_sync(0xffffffffu, sacc[kb][0], srcA);
            float p01 = __shfl_sync(0xffffffffu, sacc[kb][1], srcA);
            float p10 = __shfl_sync(0xffffffffu, sacc[kb][2], srcA);
            float p11 = __shfl_sync(0xffffffffu, sacc[kb][3], srcA);
            float s00 = __shfl_sync(0xffffffffu, sacc[kb][0], srcB);
            float s01 = __shfl_sync(0xffffffffu, sacc[kb][1], srcB);
            float s10 = __shfl_sync(0xffffffffu, sacc[kb][2], srcB);
            float s11 = __shfl_sync(0xffffffffu, sacc[kb][3], srcB);
            unsigned a0 = f2tf(odd ? p01 : p00);
            unsigned a1 = f2tf(odd ? p11 : p10);
            unsigned a2 = f2tf(odd ? s01 : s00);
            unsigned a3 = f2tf(odd ? s11 : s10);
            #pragma unroll
            for (int nb = 0; nb < 8; nb++) {
                unsigned b0 = Vs[(kb * 8 + t) * FPAD + nb * 8 + g];
                unsigned b1 = Vs[(kb * 8 + t + 4) * FPAD + nb * 8 + g];
                mma8(oacc[nb], a0, a1, a2, a3, b0, b1);
            }
        }
        __syncthreads();
    }

    // normalize and write out ([B,S,H*Dh] layout)
    float inv0 = 1.f / l0, inv1 = 1.f / l1;
    int row0 = b * SEQ + q0 + w * 16 + g;
    #pragma unroll
    for (int nb = 0; nb < 8; nb++) {
        float2 r0 = { oacc[nb][0] * inv0, oacc[nb][1] * inv0 };
        float2 r1 = { oacc[nb][2] * inv1, oacc[nb][3] * inv1 };
        *(float2*)&O[(size_t)row0 * EMBD + h * HDIM + nb * 8 + 2 * t]       = r0;
        *(float2*)&O[(size_t)(row0 + 8) * EMBD + h * HDIM + nb * 8 + 2 * t] = r1;
    }
}

// ---------------------------------------------------------------------------
extern "C" void kernel_launch(void* const* d_in, const int* in_sizes, int n_in,
                              void* d_out, int out_size)
{
    const float* x  = (const float*)d_in[0];
    const float* Wq = (const float*)d_in[1];
    const float* bq = (const float*)d_in[2];
    const float* Wk = (const float*)d_in[3];
    const float* bk = (const float*)d_in[4];
    const float* Wv = (const float*)d_in[5];
    const float* bv = (const float*)d_in[6];
    const float* Wo = (const float*)d_in[7];
    const float* bo = (const float*)d_in[8];
    float* out = (float*)d_out;

    float *Qb, *Kb, *Vb, *Ab;
    cudaGetSymbolAddress((void**)&Qb, g_Q);
    cudaGetSymbolAddress((void**)&Kb, g_K);
    cudaGetSymbolAddress((void**)&Vb, g_V);
    cudaGetSymbolAddress((void**)&Ab, g_A);

    // projections (tf32 tensor cores)
    gemm_tf32<<<dim3(EMBD / 64, MTOT / 128), 256>>>(x, Wq, bq, Qb, MTOT, EMBD, EMBD);
    gemm_tf32<<<dim3(HDIM / 64, MTOT / 128), 256>>>(x, Wk, bk, Kb, MTOT, HDIM, EMBD);
    gemm_tf32<<<dim3(HDIM / 64, MTOT / 128), 256>>>(x, Wv, bv, Vb, MTOT, HDIM, EMBD);

    // flash attention (tf32 tensor cores)
    mqa_flash_tc<<<dim3(SEQ / 64, HEADS, BATCH), 128>>>(Qb, Kb, Vb, Ab);

    // output projection
    gemm_tf32<<<dim3(EMBD / 64, MTOT / 128), 256>>>(Ab, Wo, bo, out, MTOT, EMBD, EMBD);
}

// round 3
// speedup vs baseline: 8.1832x; 1.9846x over previous
#include <cuda_runtime.h>
#include <cuda_fp16.h>

#define BATCH 4
#define SEQ   2048
#define EMBD  1024
#define HEADS 16
#define HDIM  64
#define MTOT  (BATCH*SEQ)   // 8192

// -------- scratch (static device globals; no runtime allocation) ----------
__device__ __half g_Q[MTOT*EMBD];   // Q projection (half) [B*S, E]
__device__ __half g_K[MTOT*HDIM];   // shared K (half)
__device__ __half g_V[MTOT*HDIM];   // shared V (half)
__device__ __half g_A[MTOT*EMBD];   // attention output (half), input to O-proj

// ---------------- helpers ----------------
__device__ __forceinline__ unsigned sm_u32(const void* p) {
    return (unsigned)__cvta_generic_to_shared(p);
}
__device__ __forceinline__ void ldsm4(unsigned& r0, unsigned& r1,
                                      unsigned& r2, unsigned& r3, unsigned a) {
    asm volatile("ldmatrix.sync.aligned.m8n8.x4.shared.b16 {%0,%1,%2,%3}, [%4];"
        : "=r"(r0), "=r"(r1), "=r"(r2), "=r"(r3) : "r"(a));
}
__device__ __forceinline__ void ldsm4t(unsigned& r0, unsigned& r1,
                                       unsigned& r2, unsigned& r3, unsigned a) {
    asm volatile("ldmatrix.sync.aligned.m8n8.x4.trans.shared.b16 {%0,%1,%2,%3}, [%4];"
        : "=r"(r0), "=r"(r1), "=r"(r2), "=r"(r3) : "r"(a));
}
__device__ __forceinline__ void mma16(float* c, const unsigned* a,
                                      unsigned b0, unsigned b1) {
    asm volatile(
        "mma.sync.aligned.m16n8k16.row.col.f32.f16.f16.f32 "
        "{%0,%1,%2,%3}, {%4,%5,%6,%7}, {%8,%9}, {%0,%1,%2,%3};\n"
        : "+f"(c[0]), "+f"(c[1]), "+f"(c[2]), "+f"(c[3])
        : "r"(a[0]), "r"(a[1]), "r"(a[2]), "r"(a[3]), "r"(b0), "r"(b1));
}
__device__ __forceinline__ float ex2(float x) {
    float r; asm("ex2.approx.f32 %0, %1;" : "=f"(r) : "f"(x)); return r;
}
__device__ __forceinline__ unsigned pk2(float lo, float hi) {
    __half2 h = __floats2half2_rn(lo, hi);
    return *reinterpret_cast<unsigned*>(&h);
}

// ---------------------------------------------------------------------------
// fp16 tensor-core GEMM: C[M,N] = A[M,K] @ B[K,N] + bias[N]
// BM=128, BN=64, BK=32. 256 thr = 8 warps (4m x 2n), warp tile 32x32.
// A input fp32 or fp16 (AF32); B/bias fp32; output fp32 or fp16 (OUTF32).
// ---------------------------------------------------------------------------
#define ASTR 40   // halves per As row (32 data + 8 pad)
#define BSTR 72   // halves per Bs row (64 data + 8 pad)

template<bool AF32, bool OUTF32>
__global__ __launch_bounds__(256) void gemm_h(
    const void* __restrict__ Ain, const float* __restrict__ B,
    const float* __restrict__ bias, void* __restrict__ Cout,
    int M, int N, int K)
{
    __shared__ __half As[128 * ASTR];
    __shared__ __half Bs[32 * BSTR];

    const int tid  = threadIdx.x;
    const int lane = tid & 31;
    const int w    = tid >> 5;
    const int wm   = w >> 1, wn = w & 1;
    const int g    = lane >> 2, t = lane & 3;
    const int m0   = blockIdx.y * 128;
    const int n0   = blockIdx.x * 64;

    float acc[2][4][4] = {};
    float4 paf[4]; uint4 pah[2]; float4 pbf[2];
    const int nt = K / 32;

    // ldmatrix base addresses (bytes)
    const unsigned aB = sm_u32(&As[(wm*32 + ((lane>>3)&1)*8 + (lane&7)) * ASTR
                                   + (lane>>4)*8]);
    const unsigned bB = sm_u32(&Bs[(((lane>>3)&1)*8 + (lane&7)) * BSTR
                                   + wn*32 + (lane>>4)*8]);

    // ---- prefetch tile 0 ----
    if (AF32) {
        const float* A = (const float*)Ain;
        #pragma unroll
        for (int i = 0; i < 4; i++) {
            int idx = i*256 + tid; int r = idx >> 3; int c = (idx & 7) * 4;
            paf[i] = *(const float4*)&A[(size_t)(m0 + r) * K + c];
        }
    } else {
        const __half* A = (const __half*)Ain;
        #pragma unroll
        for (int i = 0; i < 2; i++) {
            int idx = i*256 + tid; int r = idx >> 2; int c = (idx & 3) * 8;
            pah[i] = *(const uint4*)&A[(size_t)(m0 + r) * K + c];
        }
    }
    #pragma unroll
    for (int i = 0; i < 2; i++) {
        int idx = i*256 + tid; int r = idx >> 4; int c = (idx & 15) * 4;
        pbf[i] = *(const float4*)&B[(size_t)r * N + n0 + c];
    }
    // store tile 0
    if (AF32) {
        #pragma unroll
        for (int i = 0; i < 4; i++) {
            int idx = i*256 + tid; int r = idx >> 3; int c = (idx & 7) * 4;
            uint2 u = { pk2(paf[i].x, paf[i].y), pk2(paf[i].z, paf[i].w) };
            *(uint2*)&As[r * ASTR + c] = u;
        }
    } else {
        #pragma unroll
        for (int i = 0; i < 2; i++) {
            int idx = i*256 + tid; int r = idx >> 2; int c = (idx & 3) * 8;
            *(uint4*)&As[r * ASTR + c] = pah[i];
        }
    }
    #pragma unroll
    for (int i = 0; i < 2; i++) {
        int idx = i*256 + tid; int r = idx >> 4; int c = (idx & 15) * 4;
        uint2 u = { pk2(pbf[i].x, pbf[i].y), pk2(pbf[i].z, pbf[i].w) };
        *(uint2*)&Bs[r * BSTR + c] = u;
    }
    __syncthreads();

    for (int kt = 0; kt < nt; kt++) {
        if (kt + 1 < nt) {
            int k0 = (kt + 1) * 32;
            if (AF32) {
                const float* A = (const float*)Ain;
                #pragma unroll
                for (int i = 0; i < 4; i++) {
                    int idx = i*256 + tid; int r = idx >> 3; int c = (idx & 7) * 4;
                    paf[i] = *(const float4*)&A[(size_t)(m0 + r) * K + k0 + c];
                }
            } else {
                const __half* A = (const __half*)Ain;
                #pragma unroll
                for (int i = 0; i < 2; i++) {
                    int idx = i*256 + tid; int r = idx >> 2; int c = (idx & 3) * 8;
                    pah[i] = *(const uint4*)&A[(size_t)(m0 + r) * K + k0 + c];
                }
            }
            #pragma unroll
            for (int i = 0; i < 2; i++) {
                int idx = i*256 + tid; int r = idx >> 4; int c = (idx & 15) * 4;
                pbf[i] = *(const float4*)&B[(size_t)(k0 + r) * N + n0 + c];
            }
        }

        // ---- compute on current tile: 2 k16 steps ----
        #pragma unroll
        for (int k16 = 0; k16 < 2; k16++) {
            unsigned a[2][4], bb[2][4];
            #pragma unroll
            for (int mi = 0; mi < 2; mi++)
                ldsm4(a[mi][0], a[mi][1], a[mi][2], a[mi][3],
                      aB + (unsigned)(mi*16*ASTR + k16*16) * 2);
            #pragma unroll
            for (int np = 0; np < 2; np++)
                ldsm4t(bb[np][0], bb[np][1], bb[np][2], bb[np][3],
                       bB + (unsigned)(k16*16*BSTR + np*16) * 2);
            #pragma unroll
            for (int mi = 0; mi < 2; mi++)
                #pragma unroll
                for (int np = 0; np < 2; np++) {
                    mma16(acc[mi][2*np],   a[mi], bb[np][0], bb[np][1]);
                    mma16(acc[mi][2*np+1], a[mi], bb[np][2], bb[np][3]);
                }
        }

        if (kt + 1 < nt) {
            __syncthreads();
            if (AF32) {
                #pragma unroll
                for (int i = 0; i < 4; i++) {
                    int idx = i*256 + tid; int r = idx >> 3; int c = (idx & 7) * 4;
                    uint2 u = { pk2(paf[i].x, paf[i].y), pk2(paf[i].z, paf[i].w) };
                    *(uint2*)&As[r * ASTR + c] = u;
                }
            } else {
                #pragma unroll
                for (int i = 0; i < 2; i++) {
                    int idx = i*256 + tid; int r = idx >> 2; int c = (idx & 3) * 8;
                    *(uint4*)&As[r * ASTR + c] = pah[i];
                }
            }
            #pragma unroll
            for (int i = 0; i < 2; i++) {
                int idx = i*256 + tid; int r = idx >> 4; int c = (idx & 15) * 4;
                uint2 u = { pk2(pbf[i].x, pbf[i].y), pk2(pbf[i].z, pbf[i].w) };
                *(uint2*)&Bs[r * BSTR + c] = u;
            }
            __syncthreads();
        }
    }

    // ---- epilogue ----
    #pragma unroll
    for (int mi = 0; mi < 2; mi++) {
        int row = m0 + wm*32 + mi*16 + g;
        #pragma unroll
        for (int nb = 0; nb < 4; nb++) {
            int col = n0 + wn*32 + nb*8 + 2*t;
            float2 bb = *(const float2*)&bias[col];
            float v0 = acc[mi][nb][0] + bb.x, v1 = acc[mi][nb][1] + bb.y;
            float v2 = acc[mi][nb][2] + bb.x, v3 = acc[mi][nb][3] + bb.y;
            if (OUTF32) {
                float* C = (float*)Cout;
                *(float2*)&C[(size_t)row * N + col]       = make_float2(v0, v1);
                *(float2*)&C[(size_t)(row + 8) * N + col] = make_float2(v2, v3);
            } else {
                __half* C = (__half*)Cout;
                *(unsigned*)&C[(size_t)row * N + col]       = pk2(v0, v1);
                *(unsigned*)&C[(size_t)(row + 8) * N + col] = pk2(v2, v3);
            }
        }
    }
}

// ---------------------------------------------------------------------------
// Flash attention, fp16 tensor cores, multiquery (K/V shared across heads).
// CTA = (q-tile 128, head, batch), 128 thr = 4 warps; warp owns 32 q-rows.
// Q fragments register-resident; K via ldmatrix, V via ldmatrix.trans on the
// natural layout; P goes C-frag -> A-frag with one f16x2 pack (no transpose).
// ---------------------------------------------------------------------------
#define FSTR 72   // halves per smem row (64 data + 8 pad)

__global__ __launch_bounds__(128) void mqa_flash_h(
    const __half* __restrict__ Q, const __half* __restrict__ Kg,
    const __half* __restrict__ Vg, __half* __restrict__ O)
{
    __shared__ __half sm[2 * 64 * FSTR];   // Ks | Vs ; also Q staging (128 rows)
    __half* Ks = sm;
    __half* Vs = sm + 64 * FSTR;

    const int tid  = threadIdx.x;
    const int lane = tid & 31;
    const int w    = tid >> 5;
    const int g    = lane >> 2, t = lane & 3;
    const int q0   = blockIdx.x * 128;
    const int h    = blockIdx.y;
    const int b    = blockIdx.z;
    const float SC = 0.125f * 1.44269504f;   // scale * log2(e)

    // ---- stage Q tile (128 x 64 halves) and extract fragments ----
    #pragma unroll
    for (int i = 0; i < 8; i++) {
        int idx = i*128 + tid; int r = idx >> 3; int c8 = (idx & 7) * 8;
        *(uint4*)&sm[r * FSTR + c8] =
            *(const uint4*)&Q[(size_t)(b*SEQ + q0 + r) * EMBD + h*HDIM + c8];
    }
    __syncthreads();

    unsigned qf[2][4][4];
    {
        unsigned qB = sm_u32(&sm[(w*32 + ((lane>>3)&1)*8 + (lane&7)) * FSTR
                                 + (lane>>4)*8]);
        #pragma unroll
        for (int mi = 0; mi < 2; mi++)
            #pragma unroll
            for (int k16 = 0; k16 < 4; k16++)
                ldsm4(qf[mi][k16][0], qf[mi][k16][1], qf[mi][k16][2], qf[mi][k16][3],
                      qB + (unsigned)(mi*16*FSTR + k16*16) * 2);
    }
    __syncthreads();

    float oacc[2][8][4] = {};
    float mrow[2][2], lrow[2][2];
    #pragma unroll
    for (int mi = 0; mi < 2; mi++) {
        mrow[mi][0] = mrow[mi][1] = -1e30f;
        lrow[mi][0] = lrow[mi][1] = 0.f;
    }

    const unsigned kB = sm_u32(&Ks[((lane>>4)*8 + (lane&7)) * FSTR + ((lane>>3)&1)*8]);
    const unsigned vB = sm_u32(&Vs[(((lane>>3)&1)*8 + (lane&7)) * FSTR + (lane>>4)*8]);

    for (int kt = 0; kt < SEQ; kt += 64) {
        // ---- load K, V tiles (half, natural [key][dh] layout) ----
        #pragma unroll
        for (int i = 0; i < 4; i++) {
            int idx = i*128 + tid; int r = idx >> 3; int c8 = (idx & 7) * 8;
            size_t gb = (size_t)(b*SEQ + kt + r) * HDIM + c8;
            *(uint4*)&Ks[r * FSTR + c8] = *(const uint4*)&Kg[gb];
            *(uint4*)&Vs[r * FSTR + c8] = *(const uint4*)&Vg[gb];
        }
        __syncthreads();

        // ---- S = Q @ K^T ----
        float sacc[2][8][4] = {};
        #pragma unroll
        for (int k16 = 0; k16 < 4; k16++) {
            #pragma unroll
            for (int np = 0; np < 4; np++) {
                unsigned kb[4];
                ldsm4(kb[0], kb[1], kb[2], kb[3],
                      kB + (unsigned)(np*16*FSTR + k16*16) * 2);
                #pragma unroll
                for (int mi = 0; mi < 2; mi++) {
                    mma16(sacc[mi][2*np],   qf[mi][k16], kb[0], kb[1]);
                    mma16(sacc[mi][2*np+1], qf[mi][k16], kb[2], kb[3]);
                }
            }
        }

        // ---- online softmax (exp2 domain, scaled by SC) ----
        #pragma unroll
        for (int mi = 0; mi < 2; mi++) {
            float mx0 = -1e30f, mx1 = -1e30f;
            #pragma unroll
            for (int nb = 0; nb < 8; nb++) {
                mx0 = fmaxf(mx0, fmaxf(sacc[mi][nb][0], sacc[mi][nb][1]));
                mx1 = fmaxf(mx1, fmaxf(sacc[mi][nb][2], sacc[mi][nb][3]));
            }
            mx0 = fmaxf(mx0, __shfl_xor_sync(0xffffffffu, mx0, 1));
            mx0 = fmaxf(mx0, __shfl_xor_sync(0xffffffffu, mx0, 2));
            mx1 = fmaxf(mx1, __shfl_xor_sync(0xffffffffu, mx1, 1));
            mx1 = fmaxf(mx1, __shfl_xor_sync(0xffffffffu, mx1, 2));

            float mn0 = fmaxf(mrow[mi][0], mx0 * SC);
            float mn1 = fmaxf(mrow[mi][1], mx1 * SC);
            float al0 = ex2(mrow[mi][0] - mn0);
            float al1 = ex2(mrow[mi][1] - mn1);
            mrow[mi][0] = mn0; mrow[mi][1] = mn1;

            float rs0 = 0.f, rs1 = 0.f;
            #pragma unroll
            for (int nb = 0; nb < 8; nb++) {
                sacc[mi][nb][0] = ex2(fmaf(sacc[mi][nb][0], SC, -mn0));
                sacc[mi][nb][1] = ex2(fmaf(sacc[mi][nb][1], SC, -mn0));
                sacc[mi][nb][2] = ex2(fmaf(sacc[mi][nb][2], SC, -mn1));
                sacc[mi][nb][3] = ex2(fmaf(sacc[mi][nb][3], SC, -mn1));
                rs0 += sacc[mi][nb][0] + sacc[mi][nb][1];
                rs1 += sacc[mi][nb][2] + sacc[mi][nb][3];
            }
            rs0 += __shfl_xor_sync(0xffffffffu, rs0, 1);
            rs0 += __shfl_xor_sync(0xffffffffu, rs0, 2);
            rs1 += __shfl_xor_sync(0xffffffffu, rs1, 1);
            rs1 += __shfl_xor_sync(0xffffffffu, rs1, 2);

            lrow[mi][0] = lrow[mi][0] * al0 + rs0;
            lrow[mi][1] = lrow[mi][1] * al1 + rs1;
            #pragma unroll
            for (int nb = 0; nb < 8; nb++) {
                oacc[mi][nb][0] *= al0; oacc[mi][nb][1] *= al0;
                oacc[mi][nb][2] *= al1; oacc[mi][nb][3] *= al1;
            }
        }

        // ---- O += P @ V  (P: C-frag -> A-frag via f16x2 pack; V: ldmatrix.trans)
        #pragma unroll
        for (int k16 = 0; k16 < 4; k16++) {
            unsigned pa[2][4];
            #pragma unroll
            for (int mi = 0; mi < 2; mi++) {
                pa[mi][0] = pk2(sacc[mi][2*k16][0],   sacc[mi][2*k16][1]);
                pa[mi][1] = pk2(sacc[mi][2*k16][2],   sacc[mi][2*k16][3]);
                pa[mi][2] = pk2(sacc[mi][2*k16+1][0], sacc[mi][2*k16+1][1]);
                pa[mi][3] = pk2(sacc[mi][2*k16+1][2], sacc[mi][2*k16+1][3]);
            }
            #pragma unroll
            for (int np = 0; np < 4; np++) {
                unsigned vb[4];
                ldsm4t(vb[0], vb[1], vb[2], vb[3],
                       vB + (unsigned)(k16*16*FSTR + np*16) * 2);
                #pragma unroll
                for (int mi = 0; mi < 2; mi++) {
                    mma16(oacc[mi][2*np],   pa[mi], vb[0], vb[1]);
                    mma16(oacc[mi][2*np+1], pa[mi], vb[2], vb[3]);
                }
            }
        }
        __syncthreads();
    }

    // ---- normalize + store (half) ----
    #pragma unroll
    for (int mi = 0; mi < 2; mi++) {
        float i0 = 1.f / lrow[mi][0], i1 = 1.f / lrow[mi][1];
        int row = b*SEQ + q0 + w*32 + mi*16 + g;
        #pragma unroll
        for (int nb = 0; nb < 8; nb++) {
            int col = h*HDIM + nb*8 + 2*t;
            *(unsigned*)&O[(size_t)row * EMBD + col] =
                pk2(oacc[mi][nb][0] * i0, oacc[mi][nb][1] * i0);
            *(unsigned*)&O[(size_t)(row + 8) * EMBD + col] =
                pk2(oacc[mi][nb][2] * i1, oacc[mi][nb][3] * i1);
        }
    }
}

// ---------------------------------------------------------------------------
extern "C" void kernel_launch(void* const* d_in, const int* in_sizes, int n_in,
                              void* d_out, int out_size)
{
    const float* x  = (const float*)d_in[0];
    const float* Wq = (const float*)d_in[1];
    const float* bq = (const float*)d_in[2];
    const float* Wk = (const float*)d_in[3];
    const float* bk = (const float*)d_in[4];
    const float* Wv = (const float*)d_in[5];
    const float* bv = (const float*)d_in[6];
    const float* Wo = (const float*)d_in[7];
    const float* bo = (const float*)d_in[8];
    float* out = (float*)d_out;

    __half *Qb, *Kb, *Vb, *Ab;
    cudaGetSymbolAddress((void**)&Qb, g_Q);
    cudaGetSymbolAddress((void**)&Kb, g_K);
    cudaGetSymbolAddress((void**)&Vb, g_V);
    cudaGetSymbolAddress((void**)&Ab, g_A);

    // projections: fp32 in -> half out
    gemm_h<true, false><<<dim3(EMBD/64, MTOT/128), 256>>>(x, Wq, bq, Qb, MTOT, EMBD, EMBD);
    gemm_h<true, false><<<dim3(HDIM/64, MTOT/128), 256>>>(x, Wk, bk, Kb, MTOT, HDIM, EMBD);
    gemm_h<true, false><<<dim3(HDIM/64, MTOT/128), 256>>>(x, Wv, bv, Vb, MTOT, HDIM, EMBD);

    // flash attention (fp16 tensor cores)
    mqa_flash_h<<<dim3(SEQ/128, HEADS, BATCH), 128>>>(Qb, Kb, Vb, Ab);

    // output projection: half in -> fp32 out
    gemm_h<false, true><<<dim3(EMBD/64, MTOT/128), 256>>>(Ab, Wo, bo, out, MTOT, EMBD, EMBD);
}

// round 5
// speedup vs baseline: 8.7157x; 1.0651x over previous
#include <cuda_runtime.h>
#include <cuda_fp16.h>

#define BATCH 4
#define SEQ   2048
#define EMBD  1024
#define HEADS 16
#define HDIM  64
#define MTOT  (BATCH*SEQ)   // 8192

// -------- scratch (static device globals; no runtime allocation) ----------
__device__ __half g_Q[MTOT*EMBD];
__device__ __half g_K[MTOT*HDIM];
__device__ __half g_V[MTOT*HDIM];
__device__ __half g_A[MTOT*EMBD];

// ---------------- helpers ----------------
__device__ __forceinline__ unsigned sm_u32(const void* p) {
    return (unsigned)__cvta_generic_to_shared(p);
}
__device__ __forceinline__ void ldsm4(unsigned& r0, unsigned& r1,
                                      unsigned& r2, unsigned& r3, unsigned a) {
    asm volatile("ldmatrix.sync.aligned.m8n8.x4.shared.b16 {%0,%1,%2,%3}, [%4];"
        : "=r"(r0), "=r"(r1), "=r"(r2), "=r"(r3) : "r"(a));
}
__device__ __forceinline__ void ldsm4t(unsigned& r0, unsigned& r1,
                                       unsigned& r2, unsigned& r3, unsigned a) {
    asm volatile("ldmatrix.sync.aligned.m8n8.x4.trans.shared.b16 {%0,%1,%2,%3}, [%4];"
        : "=r"(r0), "=r"(r1), "=r"(r2), "=r"(r3) : "r"(a));
}
__device__ __forceinline__ void mma16(float* c, const unsigned* a,
                                      unsigned b0, unsigned b1) {
    asm volatile(
        "mma.sync.aligned.m16n8k16.row.col.f32.f16.f16.f32 "
        "{%0,%1,%2,%3}, {%4,%5,%6,%7}, {%8,%9}, {%0,%1,%2,%3};\n"
        : "+f"(c[0]), "+f"(c[1]), "+f"(c[2]), "+f"(c[3])
        : "r"(a[0]), "r"(a[1]), "r"(a[2]), "r"(a[3]), "r"(b0), "r"(b1));
}
__device__ __forceinline__ float ex2(float x) {
    float r; asm("ex2.approx.f32 %0, %1;" : "=f"(r) : "f"(x)); return r;
}
__device__ __forceinline__ unsigned pk2(float lo, float hi) {
    __half2 h = __floats2half2_rn(lo, hi);
    return *reinterpret_cast<unsigned*>(&h);
}
__device__ __forceinline__ void cpa16(unsigned dst, const void* src) {
    asm volatile("cp.async.cg.shared.global [%0], [%1], 16;"
                 :: "r"(dst), "l"(src));
}
__device__ __forceinline__ void cpa_commit() {
    asm volatile("cp.async.commit_group;");
}

// ---------------------------------------------------------------------------
// fp16 GEMM, BM=128, BN=128, BK=32. 256 thr = 8 warps (4m x 2n), warp 32x64.
// Used for the two big projections (N=1024).
// ---------------------------------------------------------------------------
#define ASTR 40    // halves per As row
#define BSTR2 136  // halves per Bs row (128 data + 8 pad)

template<bool AF32, bool OUTF32>
__global__ __launch_bounds__(256) void gemm_128(
    const void* __restrict__ Ain, const float* __restrict__ B,
    const float* __restrict__ bias, void* __restrict__ Cout,
    int M, int N, int K)
{
    __shared__ __half As[128 * ASTR];
    __shared__ __half Bs[32 * BSTR2];

    const int tid  = threadIdx.x;
    const int lane = tid & 31;
    const int w    = tid >> 5;
    const int wm   = w >> 1, wn = w & 1;
    const int g    = lane >> 2, t = lane & 3;
    const int m0   = blockIdx.y * 128;
    const int n0   = blockIdx.x * 128;

    float acc[2][8][4] = {};
    float4 paf[4]; uint4 pah[2]; float4 pbf[4];
    const int nt = K / 32;

    const unsigned aB = sm_u32(&As[(wm*32 + ((lane>>3)&1)*8 + (lane&7)) * ASTR
                                   + (lane>>4)*8]);
    const unsigned bB = sm_u32(&Bs[(((lane>>3)&1)*8 + (lane&7)) * BSTR2
                                   + wn*64 + (lane>>4)*8]);

    // ---- prefetch + store tile 0 ----
    if (AF32) {
        const float* A = (const float*)Ain;
        #pragma unroll
        for (int i = 0; i < 4; i++) {
            int idx = i*256 + tid; int r = idx >> 3; int c = (idx & 7) * 4;
            paf[i] = *(const float4*)&A[(size_t)(m0 + r) * K + c];
        }
    } else {
        const __half* A = (const __half*)Ain;
        #pragma unroll
        for (int i = 0; i < 2; i++) {
            int idx = i*256 + tid; int r = idx >> 2; int c = (idx & 3) * 8;
            pah[i] = *(const uint4*)&A[(size_t)(m0 + r) * K + c];
        }
    }
    #pragma unroll
    for (int i = 0; i < 4; i++) {
        int idx = i*256 + tid; int r = idx >> 5; int c = (idx & 31) * 4;
        pbf[i] = *(const float4*)&B[(size_t)r * N + n0 + c];
    }
    if (AF32) {
        #pragma unroll
        for (int i = 0; i < 4; i++) {
            int idx = i*256 + tid; int r = idx >> 3; int c = (idx & 7) * 4;
            uint2 u = { pk2(paf[i].x, paf[i].y), pk2(paf[i].z, paf[i].w) };
            *(uint2*)&As[r * ASTR + c] = u;
        }
    } else {
        #pragma unroll
        for (int i = 0; i < 2; i++) {
            int idx = i*256 + tid; int r = idx >> 2; int c = (idx & 3) * 8;
            *(uint4*)&As[r * ASTR + c] = pah[i];
        }
    }
    #pragma unroll
    for (int i = 0; i < 4; i++) {
        int idx = i*256 + tid; int r = idx >> 5; int c = (idx & 31) * 4;
        uint2 u = { pk2(pbf[i].x, pbf[i].y), pk2(pbf[i].z, pbf[i].w) };
        *(uint2*)&Bs[r * BSTR2 + c] = u;
    }
    __syncthreads();

    for (int kt = 0; kt < nt; kt++) {
        if (kt + 1 < nt) {
            int k0 = (kt + 1) * 32;
            if (AF32) {
                const float* A = (const float*)Ain;
                #pragma unroll
                for (int i = 0; i < 4; i++) {
                    int idx = i*256 + tid; int r = idx >> 3; int c = (idx & 7) * 4;
                    paf[i] = *(const float4*)&A[(size_t)(m0 + r) * K + k0 + c];
                }
            } else {
                const __half* A = (const __half*)Ain;
                #pragma unroll
                for (int i = 0; i < 2; i++) {
                    int idx = i*256 + tid; int r = idx >> 2; int c = (idx & 3) * 8;
                    pah[i] = *(const uint4*)&A[(size_t)(m0 + r) * K + k0 + c];
                }
            }
            #pragma unroll
            for (int i = 0; i < 4; i++) {
                int idx = i*256 + tid; int r = idx >> 5; int c = (idx & 31) * 4;
                pbf[i] = *(const float4*)&B[(size_t)(k0 + r) * N + n0 + c];
            }
        }

        #pragma unroll
        for (int k16 = 0; k16 < 2; k16++) {
            unsigned a[2][4];
            #pragma unroll
            for (int mi = 0; mi < 2; mi++)
                ldsm4(a[mi][0], a[mi][1], a[mi][2], a[mi][3],
                      aB + (unsigned)(mi*16*ASTR + k16*16) * 2);
            #pragma unroll
            for (int np = 0; np < 4; np++) {
                unsigned bb[4];
                ldsm4t(bb[0], bb[1], bb[2], bb[3],
                       bB + (unsigned)(k16*16*BSTR2 + np*16) * 2);
                #pragma unroll
                for (int mi = 0; mi < 2; mi++) {
                    mma16(acc[mi][2*np],   a[mi], bb[0], bb[1]);
                    mma16(acc[mi][2*np+1], a[mi], bb[2], bb[3]);
                }
            }
        }

        if (kt + 1 < nt) {
            __syncthreads();
            if (AF32) {
                #pragma unroll
                for (int i = 0; i < 4; i++) {
                    int idx = i*256 + tid; int r = idx >> 3; int c = (idx & 7) * 4;
                    uint2 u = { pk2(paf[i].x, paf[i].y), pk2(paf[i].z, paf[i].w) };
                    *(uint2*)&As[r * ASTR + c] = u;
                }
            } else {
                #pragma unroll
                for (int i = 0; i < 2; i++) {
                    int idx = i*256 + tid; int r = idx >> 2; int c = (idx & 3) * 8;
                    *(uint4*)&As[r * ASTR + c] = pah[i];
                }
            }
            #pragma unroll
            for (int i = 0; i < 4; i++) {
                int idx = i*256 + tid; int r = idx >> 5; int c = (idx & 31) * 4;
                uint2 u = { pk2(pbf[i].x, pbf[i].y), pk2(pbf[i].z, pbf[i].w) };
                *(uint2*)&Bs[r * BSTR2 + c] = u;
            }
            __syncthreads();
        }
    }

    #pragma unroll
    for (int mi = 0; mi < 2; mi++) {
        int row = m0 + wm*32 + mi*16 + g;
        #pragma unroll
        for (int nb = 0; nb < 8; nb++) {
            int col = n0 + wn*64 + nb*8 + 2*t;
            float2 bb = *(const float2*)&bias[col];
            float v0 = acc[mi][nb][0] + bb.x, v1 = acc[mi][nb][1] + bb.y;
            float v2 = acc[mi][nb][2] + bb.x, v3 = acc[mi][nb][3] + bb.y;
            if (OUTF32) {
                float* C = (float*)Cout;
                *(float2*)&C[(size_t)row * N + col]       = make_float2(v0, v1);
                *(float2*)&C[(size_t)(row + 8) * N + col] = make_float2(v2, v3);
            } else {
                __half* C = (__half*)Cout;
                *(unsigned*)&C[(size_t)row * N + col]       = pk2(v0, v1);
                *(unsigned*)&C[(size_t)(row + 8) * N + col] = pk2(v2, v3);
            }
        }
    }
}

// ---------------------------------------------------------------------------
// fp16 GEMM, BM=128, BN=64 (for the narrow K/V projections).
// ---------------------------------------------------------------------------
#define BSTR 72

__global__ __launch_bounds__(256) void gemm_64(
    const float* __restrict__ A, const float* __restrict__ B,
    const float* __restrict__ bias, __half* __restrict__ C,
    int M, int N, int K)
{
    __shared__ __half As[128 * ASTR];
    __shared__ __half Bs[32 * BSTR];

    const int tid  = threadIdx.x;
    const int lane = tid & 31;
    const int w    = tid >> 5;
    const int wm   = w >> 1, wn = w & 1;
    const int g    = lane >> 2, t = lane & 3;
    const int m0   = blockIdx.y * 128;
    const int n0   = blockIdx.x * 64;

    float acc[2][4][4] = {};
    float4 paf[4]; float4 pbf[2];
    const int nt = K / 32;

    const unsigned aB = sm_u32(&As[(wm*32 + ((lane>>3)&1)*8 + (lane&7)) * ASTR
                                   + (lane>>4)*8]);
    const unsigned bB = sm_u32(&Bs[(((lane>>3)&1)*8 + (lane&7)) * BSTR
                                   + wn*32 + (lane>>4)*8]);

    #pragma unroll
    for (int i = 0; i < 4; i++) {
        int idx = i*256 + tid; int r = idx >> 3; int c = (idx & 7) * 4;
        paf[i] = *(const float4*)&A[(size_t)(m0 + r) * K + c];
    }
    #pragma unroll
    for (int i = 0; i < 2; i++) {
        int idx = i*256 + tid; int r = idx >> 4; int c = (idx & 15) * 4;
        pbf[i] = *(const float4*)&B[(size_t)r * N + n0 + c];
    }
    #pragma unroll
    for (int i = 0; i < 4; i++) {
        int idx = i*256 + tid; int r = idx >> 3; int c = (idx & 7) * 4;
        uint2 u = { pk2(paf[i].x, paf[i].y), pk2(paf[i].z, paf[i].w) };
        *(uint2*)&As[r * ASTR + c] = u;
    }
    #pragma unroll
    for (int i = 0; i < 2; i++) {
        int idx = i*256 + tid; int r = idx >> 4; int c = (idx & 15) * 4;
        uint2 u = { pk2(pbf[i].x, pbf[i].y), pk2(pbf[i].z, pbf[i].w) };
        *(uint2*)&Bs[r * BSTR + c] = u;
    }
    __syncthreads();

    for (int kt = 0; kt < nt; kt++) {
        if (kt + 1 < nt) {
            int k0 = (kt + 1) * 32;
            #pragma unroll
            for (int i = 0; i < 4; i++) {
                int idx = i*256 + tid; int r = idx >> 3; int c = (idx & 7) * 4;
                paf[i] = *(const float4*)&A[(size_t)(m0 + r) * K + k0 + c];
            }
            #pragma unroll
            for (int i = 0; i < 2; i++) {
                int idx = i*256 + tid; int r = idx >> 4; int c = (idx & 15) * 4;
                pbf[i] = *(const float4*)&B[(size_t)(k0 + r) * N + n0 + c];
            }
        }
        #pragma unroll
        for (int k16 = 0; k16 < 2; k16++) {
            unsigned a[2][4], bb[2][4];
            #pragma unroll
            for (int mi = 0; mi < 2; mi++)
                ldsm4(a[mi][0], a[mi][1], a[mi][2], a[mi][3],
                      aB + (unsigned)(mi*16*ASTR + k16*16) * 2);
            #pragma unroll
            for (int np = 0; np < 2; np++)
                ldsm4t(bb[np][0], bb[np][1], bb[np][2], bb[np][3],
                       bB + (unsigned)(k16*16*BSTR + np*16) * 2);
            #pragma unroll
            for (int mi = 0; mi < 2; mi++)
                #pragma unroll
                for (int np = 0; np < 2; np++) {
                    mma16(acc[mi][2*np],   a[mi], bb[np][0], bb[np][1]);
                    mma16(acc[mi][2*np+1], a[mi], bb[np][2], bb[np][3]);
                }
        }
        if (kt + 1 < nt) {
            __syncthreads();
            #pragma unroll
            for (int i = 0; i < 4; i++) {
                int idx = i*256 + tid; int r = idx >> 3; int c = (idx & 7) * 4;
                uint2 u = { pk2(paf[i].x, paf[i].y), pk2(paf[i].z, paf[i].w) };
                *(uint2*)&As[r * ASTR + c] = u;
            }
            #pragma unroll
            for (int i = 0; i < 2; i++) {
                int idx = i*256 + tid; int r = idx >> 4; int c = (idx & 15) * 4;
                uint2 u = { pk2(pbf[i].x, pbf[i].y), pk2(pbf[i].z, pbf[i].w) };
                *(uint2*)&Bs[r * BSTR + c] = u;
            }
            __syncthreads();
        }
    }

    #pragma unroll
    for (int mi = 0; mi < 2; mi++) {
        int row = m0 + wm*32 + mi*16 + g;
        #pragma unroll
        for (int nb = 0; nb < 4; nb++) {
            int col = n0 + wn*32 + nb*8 + 2*t;
            float2 bb = *(const float2*)&bias[col];
            *(unsigned*)&C[(size_t)row * N + col] =
                pk2(acc[mi][nb][0] + bb.x, acc[mi][nb][1] + bb.y);
            *(unsigned*)&C[(size_t)(row + 8) * N + col] =
                pk2(acc[mi][nb][2] + bb.x, acc[mi][nb][3] + bb.y);
        }
    }
}

// ---------------------------------------------------------------------------
// Flash attention, fp16 MMA, cp.async double-buffered K/V, MQA.
// CTA = (q-tile 64, head, batch); 128 thr = 4 warps; warp owns 16 q-rows.
// 3 CTAs/SM target (launch_bounds reg cap).
// ---------------------------------------------------------------------------
#define FSTR 72
#define BUFH (128 * FSTR)          // halves per (K+V) buffer
#define BUFB (BUFH * 2)            // bytes per buffer

__global__ __launch_bounds__(128, 3) void mqa_flash_h2(
    const __half* __restrict__ Q, const __half* __restrict__ Kg,
    const __half* __restrict__ Vg, __half* __restrict__ O)
{
    __shared__ __half sm[2 * BUFH];   // buf0: Ks|Vs, buf1: Ks|Vs (Q staged in buf1)

    const int tid  = threadIdx.x;
    const int lane = tid & 31;
    const int w    = tid >> 5;
    const int g    = lane >> 2, t = lane & 3;
    const int q0   = blockIdx.x * 64;
    const int h    = blockIdx.y;
    const int b    = blockIdx.z;
    const float SC = 0.125f * 1.44269504f;

    const unsigned smBase = sm_u32(sm);
    const size_t kvRow0 = (size_t)b * SEQ * HDIM;

    // ---- issue cp.async for tile 0 into buf0 ----
    {
        #pragma unroll
        for (int i = 0; i < 4; i++) {
            int idx = i*128 + tid; int r = idx >> 3; int c8 = (idx & 7) * 8;
            unsigned dK = smBase + (unsigned)(r*FSTR + c8) * 2;
            unsigned dV = dK + (unsigned)(64*FSTR) * 2;
            size_t gofs = kvRow0 + (size_t)r * HDIM + c8;
            cpa16(dK, Kg + gofs);
            cpa16(dV, Vg + gofs);
        }
        cpa_commit();
    }

    // ---- stage Q (64 x 64) into buf1 region, extract fragments ----
    __half* Qst = sm + BUFH;
    #pragma unroll
    for (int i = 0; i < 4; i++) {
        int idx = i*128 + tid; int r = idx >> 3; int c8 = (idx & 7) * 8;
        *(uint4*)&Qst[r * FSTR + c8] =
            *(const uint4*)&Q[(size_t)(b*SEQ + q0 + r) * EMBD + h*HDIM + c8];
    }
    __syncthreads();

    unsigned qf[4][4];
    {
        unsigned qB = sm_u32(&Qst[(w*16 + ((lane>>3)&1)*8 + (lane&7)) * FSTR
                                  + (lane>>4)*8]);
        #pragma unroll
        for (int k16 = 0; k16 < 4; k16++)
            ldsm4(qf[k16][0], qf[k16][1], qf[k16][2], qf[k16][3],
                  qB + (unsigned)(k16*16) * 2);
    }
    __syncthreads();   // Q frags extracted before buf1 is overwritten by tile 1

    float oacc[8][4] = {};
    float m0v = -1e30f, m1v = -1e30f, l0 = 0.f, l1 = 0.f;

    // lane-invariant parts of ldsm addresses (relative to buffer base)
    const unsigned kRel = (unsigned)(((lane>>4)*8 + (lane&7)) * FSTR
                                     + ((lane>>3)&1)*8) * 2;
    const unsigned vRel = (unsigned)((((lane>>3)&1)*8 + (lane&7)) * FSTR
                                     + (lane>>4)*8) * 2 + (unsigned)(64*FSTR)*2;

    const int nt = SEQ / 64;
    for (int kt = 0; kt < nt; kt++) {
        // prefetch next tile into the other buffer
        if (kt + 1 < nt) {
            unsigned bufB = (unsigned)((kt + 1) & 1) * BUFB;
            size_t rowB = kvRow0 + (size_t)(kt + 1) * 64 * HDIM;
            #pragma unroll
            for (int i = 0; i < 4; i++) {
                int idx = i*128 + tid; int r = idx >> 3; int c8 = (idx & 7) * 8;
                unsigned dK = smBase + bufB + (unsigned)(r*FSTR + c8) * 2;
                unsigned dV = dK + (unsigned)(64*FSTR) * 2;
                size_t gofs = rowB + (size_t)r * HDIM + c8;
                cpa16(dK, Kg + gofs);
                cpa16(dV, Vg + gofs);
            }
            cpa_commit();
            asm volatile("cp.async.wait_group 1;");
        } else {
            asm volatile("cp.async.wait_group 0;");
        }
        __syncthreads();

        const unsigned kB = smBase + (unsigned)(kt & 1) * BUFB + kRel;
        const unsigned vB = smBase + (unsigned)(kt & 1) * BUFB + vRel;

        // ---- S = Q @ K^T (warp 16 x 64) ----
        float sacc[8][4] = {};
        #pragma unroll
        for (int k16 = 0; k16 < 4; k16++) {
            #pragma unroll
            for (int np = 0; np < 4; np++) {
                unsigned kb[4];
                ldsm4(kb[0], kb[1], kb[2], kb[3],
                      kB + (unsigned)(np*16*FSTR + k16*16) * 2);
                mma16(sacc[2*np],   qf[k16], kb[0], kb[1]);
                mma16(sacc[2*np+1], qf[k16], kb[2], kb[3]);
            }
        }

        // ---- online softmax (exp2 domain) ----
        float mx0 = -1e30f, mx1 = -1e30f;
        #pragma unroll
        for (int nb = 0; nb < 8; nb++) {
            mx0 = fmaxf(mx0, fmaxf(sacc[nb][0], sacc[nb][1]));
            mx1 = fmaxf(mx1, fmaxf(sacc[nb][2], sacc[nb][3]));
        }
        mx0 = fmaxf(mx0, __shfl_xor_sync(0xffffffffu, mx0, 1));
        mx0 = fmaxf(mx0, __shfl_xor_sync(0xffffffffu, mx0, 2));
        mx1 = fmaxf(mx1, __shfl_xor_sync(0xffffffffu, mx1, 1));
        mx1 = fmaxf(mx1, __shfl_xor_sync(0xffffffffu, mx1, 2));

        float mn0 = fmaxf(m0v, mx0 * SC);
        float mn1 = fmaxf(m1v, mx1 * SC);
        float al0 = ex2(m0v - mn0);
        float al1 = ex2(m1v - mn1);
        m0v = mn0; m1v = mn1;

        float rs0 = 0.f, rs1 = 0.f;
        #pragma unroll
        for (int nb = 0; nb < 8; nb++) {
            sacc[nb][0] = ex2(fmaf(sacc[nb][0], SC, -mn0));
            sacc[nb][1] = ex2(fmaf(sacc[nb][1], SC, -mn0));
            sacc[nb][2] = ex2(fmaf(sacc[nb][2], SC, -mn1));
            sacc[nb][3] = ex2(fmaf(sacc[nb][3], SC, -mn1));
            rs0 += sacc[nb][0] + sacc[nb][1];
            rs1 += sacc[nb][2] + sacc[nb][3];
        }
        rs0 += __shfl_xor_sync(0xffffffffu, rs0, 1);
        rs0 += __shfl_xor_sync(0xffffffffu, rs0, 2);
        rs1 += __shfl_xor_sync(0xffffffffu, rs1, 1);
        rs1 += __shfl_xor_sync(0xffffffffu, rs1, 2);

        l0 = l0 * al0 + rs0;
        l1 = l1 * al1 + rs1;
        #pragma unroll
        for (int nb = 0; nb < 8; nb++) {
            oacc[nb][0] *= al0; oacc[nb][1] *= al0;
            oacc[nb][2] *= al1; oacc[nb][3] *= al1;
        }

        // ---- O += P @ V (P: C-frag == A-frag after f16 pack) ----
        #pragma unroll
        for (int k16 = 0; k16 < 4; k16++) {
            unsigned pa[4];
            pa[0] = pk2(sacc[2*k16][0],   sacc[2*k16][1]);
            pa[1] = pk2(sacc[2*k16][2],   sacc[2*k16][3]);
            pa[2] = pk2(sacc[2*k16+1][0], sacc[2*k16+1][1]);
            pa[3] = pk2(sacc[2*k16+1][2], sacc[2*k16+1][3]);
            #pragma unroll
            for (int np = 0; np < 4; np++) {
                unsigned vb[4];
                ldsm4t(vb[0], vb[1], vb[2], vb[3],
                       vB + (unsigned)(k16*16*FSTR + np*16) * 2);
                mma16(oacc[2*np],   pa, vb[0], vb[1]);
                mma16(oacc[2*np+1], pa, vb[2], vb[3]);
            }
        }
        __syncthreads();
    }

    // ---- normalize + store ----
    float i0 = 1.f / l0, i1 = 1.f / l1;
    int row = b*SEQ + q0 + w*16 + g;
    #pragma unroll
    for (int nb = 0; nb < 8; nb++) {
        int col = h*HDIM + nb*8 + 2*t;
        *(unsigned*)&O[(size_t)row * EMBD + col] =
            pk2(oacc[nb][0] * i0, oacc[nb][1] * i0);
        *(unsigned*)&O[(size_t)(row + 8) * EMBD + col] =
            pk2(oacc[nb][2] * i1, oacc[nb][3] * i1);
    }
}

// ---------------------------------------------------------------------------
extern "C" void kernel_launch(void* const* d_in, const int* in_sizes, int n_in,
                              void* d_out, int out_size)
{
    const float* x  = (const float*)d_in[0];
    const float* Wq = (const float*)d_in[1];
    const float* bq = (const float*)d_in[2];
    const float* Wk = (const float*)d_in[3];
    const float* bk = (const float*)d_in[4];
    const float* Wv = (const float*)d_in[5];
    const float* bv = (const float*)d_in[6];
    const float* Wo = (const float*)d_in[7];
    const float* bo = (const float*)d_in[8];
    float* out = (float*)d_out;

    __half *Qb, *Kb, *Vb, *Ab;
    cudaGetSymbolAddress((void**)&Qb, g_Q);
    cudaGetSymbolAddress((void**)&Kb, g_K);
    cudaGetSymbolAddress((void**)&Vb, g_V);
    cudaGetSymbolAddress((void**)&Ab, g_A);

    gemm_128<true,  false><<<dim3(EMBD/128, MTOT/128), 256>>>(x, Wq, bq, Qb, MTOT, EMBD, EMBD);
    gemm_64<<<dim3(1, MTOT/128), 256>>>(x, Wk, bk, Kb, MTOT, HDIM, EMBD);
    gemm_64<<<dim3(1, MTOT/128), 256>>>(x, Wv, bv, Vb, MTOT, HDIM, EMBD);

    mqa_flash_h2<<<dim3(SEQ/64, HEADS, BATCH), 128>>>(Qb, Kb, Vb, Ab);

    gemm_128<false, true><<<dim3(EMBD/128, MTOT/128), 256>>>(Ab, Wo, bo, out, MTOT, EMBD, EMBD);
}